// round 13
// baseline (speedup 1.0000x reference)
#include <cuda_runtime.h>
#include <cuda_bf16.h>
#include <math.h>
#include <stdint.h>

// Problem constants
#define M_ROWS 8192      // B*H*W
#define N_E    8192
#define E_DIM  512

// Output layout (flattened tuple, fp32)
#define OFF_PROB ((size_t)3)
#define OFF_D    (OFF_PROB + (size_t)M_ROWS * N_E)
#define OFF_ZQ   (OFF_D    + (size_t)M_ROWS * N_E)
#define OFF_PERP (OFF_ZQ   + (size_t)M_ROWS * E_DIM)
#define OFF_MINE (OFF_PERP + 1)      // divisible by 4 -> float4 stores legal
#define OFF_IDX  (OFF_MINE + (size_t)M_ROWS * N_E)

// ---------------------------------------------------------------------------
// Device scratch (no dynamic allocation allowed)
// ---------------------------------------------------------------------------
static __device__ float g_cbnorm[N_E];
static __device__ float g_winv[N_E];       // 1/||w_row|| : z_q = w*winv
static __device__ float g_znorm[M_ROWS];
static __device__ int   g_counts[N_E];
static __device__ float g_cos[M_ROWS];
// bf16 hi/lo splits for tensor-core GEMM
static __device__ __align__(16) __nv_bfloat16 g_zhi[(size_t)M_ROWS * E_DIM];
static __device__ __align__(16) __nv_bfloat16 g_zlo[(size_t)M_ROWS * E_DIM];
static __device__ __align__(16) __nv_bfloat16 g_bhi[(size_t)N_E   * E_DIM];
static __device__ __align__(16) __nv_bfloat16 g_blo[(size_t)N_E   * E_DIM];

// ---------------------------------------------------------------------------
// PTX helpers (base ISA only: mma.sync / ldmatrix / cp.async)
// ---------------------------------------------------------------------------
__device__ __forceinline__ uint32_t smem_u32(const void* p) {
    uint32_t a;
    asm("{ .reg .u64 t; cvta.to.shared.u64 t, %1; cvt.u32.u64 %0, t; }"
        : "=r"(a) : "l"(p));
    return a;
}
__device__ __forceinline__ void cp16(uint32_t saddr, const void* g) {
    asm volatile("cp.async.cg.shared.global [%0], [%1], 16;"
                 :: "r"(saddr), "l"(g) : "memory");
}
__device__ __forceinline__ void ldsm4(uint32_t* r, uint32_t addr) {
    asm volatile("ldmatrix.sync.aligned.m8n8.x4.shared.b16 {%0,%1,%2,%3}, [%4];"
                 : "=r"(r[0]), "=r"(r[1]), "=r"(r[2]), "=r"(r[3]) : "r"(addr));
}
__device__ __forceinline__ void mma_bf16(float* c, const uint32_t* a, const uint32_t* b) {
    asm volatile(
        "mma.sync.aligned.m16n8k16.row.col.f32.bf16.bf16.f32 "
        "{%0,%1,%2,%3}, {%4,%5,%6,%7}, {%8,%9}, {%0,%1,%2,%3};"
        : "+f"(c[0]), "+f"(c[1]), "+f"(c[2]), "+f"(c[3])
        : "r"(a[0]), "r"(a[1]), "r"(a[2]), "r"(a[3]), "r"(b[0]), "r"(b[1]));
}

// ---------------------------------------------------------------------------
// Fused prep: blocks [0, N_E) normalize codebook rows (bf16 splits + norms,
// no fp32 cb array); blocks [N_E, N_E+M) split z rows.
// ---------------------------------------------------------------------------
__global__ __launch_bounds__(256) void prep_kernel(const float* __restrict__ w,
                                                   const float* __restrict__ z) {
    int b = blockIdx.x;
    int t = threadIdx.x;
    __shared__ float sm[256];

    if (b < N_E) {
        int r = b;
        const float* row = w + (size_t)r * E_DIM;
        float v0 = row[t];
        float v1 = row[t + 256];

        sm[t] = v0 * v0 + v1 * v1;
        __syncthreads();
        #pragma unroll
        for (int s = 128; s > 0; s >>= 1) {
            if (t < s) sm[t] += sm[t + s];
            __syncthreads();
        }
        float norm = sqrtf(sm[0]);
        __syncthreads();

        float c0 = v0 / norm;
        float c1 = v1 / norm;
        size_t base = (size_t)r * E_DIM;

        __nv_bfloat16 h0 = __float2bfloat16(c0);
        __nv_bfloat16 h1 = __float2bfloat16(c1);
        g_bhi[base + t]       = h0;
        g_bhi[base + t + 256] = h1;
        g_blo[base + t]       = __float2bfloat16(c0 - __bfloat162float(h0));
        g_blo[base + t + 256] = __float2bfloat16(c1 - __bfloat162float(h1));

        sm[t] = c0 * c0 + c1 * c1;
        __syncthreads();
        #pragma unroll
        for (int s = 128; s > 0; s >>= 1) {
            if (t < s) sm[t] += sm[t + s];
            __syncthreads();
        }
        if (t == 0) {
            g_cbnorm[r] = sqrtf(sm[0]);
            g_winv[r]   = 1.0f / norm;
        }
    } else {
        int r = b - N_E;
        const float* row = z + (size_t)r * E_DIM;
        float v0 = row[t];
        float v1 = row[t + 256];

        size_t base = (size_t)r * E_DIM;
        __nv_bfloat16 h0 = __float2bfloat16(v0);
        __nv_bfloat16 h1 = __float2bfloat16(v1);
        g_zhi[base + t]       = h0;
        g_zhi[base + t + 256] = h1;
        g_zlo[base + t]       = __float2bfloat16(v0 - __bfloat162float(h0));
        g_zlo[base + t + 256] = __float2bfloat16(v1 - __bfloat162float(h1));

        if (r < N_E / 256) g_counts[r * 256 + t] = 0;

        sm[t] = v0 * v0 + v1 * v1;
        __syncthreads();
        #pragma unroll
        for (int s = 128; s > 0; s >>= 1) {
            if (t < s) sm[t] += sm[t + s];
            __syncthreads();
        }
        if (t == 0) g_znorm[r] = sqrtf(sm[0]);
    }
}

// ---------------------------------------------------------------------------
// mma.sync GEMM (3-term bf16 split): tile 128x128, K chunks of 32,
// 3-stage cp.async pipeline, loads issued 2 chunks ahead.
// XOR swizzle on 64B rows. 96KB smem/CTA -> 2 CTAs/SM.
// min_encodings zeroing interleaved into mainloop.
// ---------------------------------------------------------------------------
#define BM 128
#define BN 128
#define KC 32
#define NCHUNK (E_DIM / KC)        // 16
#define ROWB 64
#define ARR_SZ (128 * ROWB)        // 8192
#define STAGE_SZ (4 * ARR_SZ)      // 32768
#define NSTAGE 3
#define GEMM_SMEM (NSTAGE * STAGE_SZ)  // 98304

__device__ __forceinline__ uint32_t swz(uint32_t row, uint32_t c16) {
    return row * ROWB + (((c16 ^ (row >> 1)) & 3u) << 4);
}

__global__ __launch_bounds__(256, 2) void mma_gemm_kernel(float* __restrict__ out) {
    extern __shared__ char smem[];
    const uint32_t sbase = smem_u32(smem);
    const int tid = threadIdx.x;
    const int lane = tid & 31;
    const int wid = tid >> 5;
    const int wm = wid & 3;
    const int wn = wid >> 2;
    const int r0 = blockIdx.y * BM;
    const int c0 = blockIdx.x * BN;

    float acc[2][8][4];
    #pragma unroll
    for (int a = 0; a < 2; a++)
        #pragma unroll
        for (int b = 0; b < 8; b++)
            #pragma unroll
            for (int e = 0; e < 4; e++) acc[a][b][e] = 0.0f;

    auto load_chunk = [&](int c, int stage) {
        uint32_t sb = sbase + (uint32_t)stage * STAGE_SZ;
        #pragma unroll
        for (int i = 0; i < 2; i++) {
            int slot = tid + i * 256;
            uint32_t row = (uint32_t)slot >> 2;
            uint32_t u   = (uint32_t)slot & 3;
            uint32_t so = swz(row, u);
            size_t ga = (size_t)(r0 + row) * E_DIM + c * KC + u * 8;
            size_t gb = (size_t)(c0 + row) * E_DIM + c * KC + u * 8;
            cp16(sb + so,              g_zhi + ga);
            cp16(sb + ARR_SZ + so,     g_zlo + ga);
            cp16(sb + 2 * ARR_SZ + so, g_bhi + gb);
            cp16(sb + 3 * ARR_SZ + so, g_blo + gb);
        }
        asm volatile("cp.async.commit_group;" ::: "memory");
    };

    const uint32_t rowA = (uint32_t)(wm * 32 + (lane & 15));
    const uint32_t rowB = (uint32_t)(wn * 64 + (lane & 7) + ((lane >> 4) << 3));
    const uint32_t xA = (rowA >> 1) & 3u;
    const uint32_t xB = (rowB >> 1) & 3u;
    const uint32_t cA0 = (uint32_t)(lane >> 4);
    const uint32_t cB0 = (uint32_t)((lane >> 3) & 1);
    const uint32_t aBase = rowA * ROWB;
    const uint32_t bBase = rowB * ROWB;

    auto compute = [&](int stage) {
        uint32_t sb = sbase + (uint32_t)stage * STAGE_SZ;
        uint32_t Ahi = sb;
        uint32_t Alo = sb + ARR_SZ;
        uint32_t Bhi = sb + 2 * ARR_SZ;
        uint32_t Blo = sb + 3 * ARR_SZ;
        #pragma unroll
        for (int ks = 0; ks < 2; ks++) {
            uint32_t aOff = aBase + (((cA0 + 2 * ks) ^ xA) & 3u) * 16;
            uint32_t bOff = bBase + (((cB0 + 2 * ks) ^ xB) & 3u) * 16;

            uint32_t ah[2][4], al[2][4];
            ldsm4(ah[0], Ahi + aOff);
            ldsm4(ah[1], Ahi + aOff + 16 * ROWB);
            ldsm4(al[0], Alo + aOff);
            ldsm4(al[1], Alo + aOff + 16 * ROWB);

            uint32_t bh[2][4], bl[2][4];
            ldsm4(bh[0], Bhi + bOff);
            ldsm4(bl[0], Blo + bOff);

            #pragma unroll
            for (int np = 0; np < 4; np++) {
                const int cur = np & 1;
                const int nxt = cur ^ 1;
                if (np < 3) {
                    ldsm4(bh[nxt], Bhi + bOff + (np + 1) * 16 * ROWB);
                    ldsm4(bl[nxt], Blo + bOff + (np + 1) * 16 * ROWB);
                }
                #pragma unroll
                for (int mt = 0; mt < 2; mt++)
                    #pragma unroll
                    for (int s = 0; s < 2; s++)
                        mma_bf16(acc[mt][np * 2 + s], ah[mt], bh[cur] + 2 * s);  // hi*hi
                #pragma unroll
                for (int mt = 0; mt < 2; mt++)
                    #pragma unroll
                    for (int s = 0; s < 2; s++)
                        mma_bf16(acc[mt][np * 2 + s], al[mt], bh[cur] + 2 * s);  // lo*hi
                #pragma unroll
                for (int mt = 0; mt < 2; mt++)
                    #pragma unroll
                    for (int s = 0; s < 2; s++)
                        mma_bf16(acc[mt][np * 2 + s], ah[mt], bl[cur] + 2 * s);  // hi*lo
            }
        }
    };

    float* MINE = out + OFF_MINE;
    const int zrow = wid;
    const int zcol = lane * 4;

    load_chunk(0, 0);
    load_chunk(1, 1);
    #pragma unroll 1
    for (int c = 0; c < NCHUNK; c++) {
        if (c + 1 < NCHUNK) {
            asm volatile("cp.async.wait_group 1;" ::: "memory");
        } else {
            asm volatile("cp.async.wait_group 0;" ::: "memory");
        }
        __syncthreads();
        if (c + 2 < NCHUNK) load_chunk(c + 2, (c + 2) % NSTAGE);
        {
            float4 z4 = make_float4(0.f, 0.f, 0.f, 0.f);
            *reinterpret_cast<float4*>(
                MINE + (size_t)(r0 + c * 8 + zrow) * N_E + c0 + zcol) = z4;
        }
        compute(c % NSTAGE);
    }

    float* D = out + OFF_D;
    const int gr = lane >> 2;
    const int gc = (lane & 3) * 2;
    #pragma unroll
    for (int mt = 0; mt < 2; mt++) {
        int rA = r0 + wm * 32 + mt * 16 + gr;
        int rB = rA + 8;
        float znA = g_znorm[rA];
        float znB = g_znorm[rB];
        #pragma unroll
        for (int n8 = 0; n8 < 8; n8++) {
            int cc = c0 + wn * 64 + n8 * 8 + gc;
            float cn0 = g_cbnorm[cc];
            float cn1 = g_cbnorm[cc + 1];
            float* a4 = acc[mt][n8];
            D[(size_t)rA * N_E + cc]     = a4[0] / (znA * cn0 + 1e-6f);
            D[(size_t)rA * N_E + cc + 1] = a4[1] / (znA * cn1 + 1e-6f);
            D[(size_t)rB * N_E + cc]     = a4[2] / (znB * cn0 + 1e-6f);
            D[(size_t)rB * N_E + cc + 1] = a4[3] / (znB * cn1 + 1e-6f);
        }
    }
}

// ---------------------------------------------------------------------------
// Polynomial exp on [-1,1] (degree-10 Taylor, FMA pipe; avoids MUFU wall)
// ---------------------------------------------------------------------------
__device__ __forceinline__ float exp_poly(float x) {
    const float c10 = 2.7557319e-7f, c9 = 2.7557319e-6f, c8 = 2.4801587e-5f;
    const float c7 = 1.9841270e-4f,  c6 = 1.3888889e-3f, c5 = 8.3333333e-3f;
    const float c4 = 4.1666668e-2f,  c3 = 1.6666667e-1f, c2 = 0.5f;
    float p = c10;
    p = fmaf(p, x, c9);
    p = fmaf(p, x, c8);
    p = fmaf(p, x, c7);
    p = fmaf(p, x, c6);
    p = fmaf(p, x, c5);
    p = fmaf(p, x, c4);
    p = fmaf(p, x, c3);
    p = fmaf(p, x, c2);
    p = fmaf(p, x, 1.0f);
    p = fmaf(p, x, 1.0f);
    return p;
}

// ---------------------------------------------------------------------------
// Fused per-row (256 threads, TWO-PASS — no e[] register cache, so regs drop
// and occupancy rises; second d read hits L2): argmax (first-index
// tie-break), histogram, idx, one-hot 1.0, softmax (poly exp, shift-free),
// z_q row = w[idx]*winv[idx], cosine via rescale identity.
// ---------------------------------------------------------------------------
__global__ __launch_bounds__(256) void softmax_kernel(float* __restrict__ out,
                                                      const float* __restrict__ w) {
    __shared__ float sred[256];
    __shared__ int   sidx[256];

    int r = blockIdx.x;
    int t = threadIdx.x;
    const float* drow = out + OFF_D + (size_t)r * N_E;

    // pass 1: max/argmax + exp sum (no caching)
    float best = -2.0f;
    int bi = 0;
    float sum = 0.0f;
    #pragma unroll 4
    for (int j = 0; j < 32; j++) {
        int i = t + j * 256;
        float v = drow[i];
        if (v > best) { best = v; bi = i; }   // j ascending => first index kept
        sum += exp_poly(v);
    }
    sred[t] = best; sidx[t] = bi;
    __syncthreads();
    for (int s = 128; s > 0; s >>= 1) {
        if (t < s) {
            float v = sred[t + s]; int ii = sidx[t + s];
            if (v > sred[t] || (v == sred[t] && ii < sidx[t])) {
                sred[t] = v; sidx[t] = ii;
            }
        }
        __syncthreads();
    }
    int idx = sidx[0];
    if (t == 0) {
        atomicAdd(&g_counts[idx], 1);
        out[OFF_IDX + r] = (float)idx;
        out[OFF_MINE + (size_t)r * N_E + idx] = 1.0f;
        float zn  = g_znorm[r];
        float cbn = g_cbnorm[idx];
        float p   = zn * cbn;
        g_cos[r] = sred[0] * (p + 1e-6f) / p;
    }

    // z_q_st row = w[idx] * (1/||w[idx]||)  (identical arithmetic to cb[idx])
    {
        float winv = g_winv[idx];
        const float* wrow = w + (size_t)idx * E_DIM;
        float* o = out + OFF_ZQ + (size_t)r * E_DIM;
        o[t]       = wrow[t] * winv;
        o[t + 256] = wrow[t + 256] * winv;
    }

    __syncthreads();
    sred[t] = sum;
    __syncthreads();
    for (int s = 128; s > 0; s >>= 1) {
        if (t < s) sred[t] += sred[t + s];
        __syncthreads();
    }
    float inv = 1.0f / sred[0];

    // pass 2: recompute exp (d re-read hits L2), write prob
    float* prow = out + OFF_PROB + (size_t)r * N_E;
    #pragma unroll 4
    for (int j = 0; j < 32; j++) {
        int i = t + j * 256;
        prow[i] = exp_poly(drow[i]) * inv;
    }
}

// ---------------------------------------------------------------------------
// Scalars — 1024 threads so the logf chains parallelize.
// ---------------------------------------------------------------------------
__global__ __launch_bounds__(1024) void finalize_kernel(float* __restrict__ out) {
    int t = threadIdx.x;
    __shared__ float s1[1024], s2[1024], s3[1024];

    float kl = 0.0f, ent = 0.0f, cs = 0.0f;
    const float invM  = 1.0f / (float)M_ROWS;
    const float invNE = 1.0f / (float)N_E;
    #pragma unroll
    for (int j = t; j < N_E; j += 1024) {
        float em = (float)g_counts[j] * invM;
        kl  += em * logf(invNE / (em + 1e-6f));
        ent += em * logf(em + 1e-6f);
    }
    #pragma unroll
    for (int j = t; j < M_ROWS; j += 1024) cs += g_cos[j];

    s1[t] = kl; s2[t] = ent; s3[t] = cs;
    __syncthreads();
    for (int s = 512; s > 0; s >>= 1) {
        if (t < s) { s1[t] += s1[t + s]; s2[t] += s2[t + s]; s3[t] += s3[t + s]; }
        __syncthreads();
    }
    if (t == 0) {
        float mc = s3[0] * invM;
        out[0] = (1.0f - mc) + 0.25f * (1.0f - mc);
        out[1] = 0.0f;
        out[2] = -s1[0];
        out[OFF_PERP] = expf(-s2[0]);
    }
}

// ---------------------------------------------------------------------------
extern "C" void kernel_launch(void* const* d_in, const int* in_sizes, int n_in,
                              void* d_out, int out_size) {
    const float* z = (const float*)d_in[0];
    const float* w = (const float*)d_in[1];
    float* out = (float*)d_out;

    cudaFuncSetAttribute(mma_gemm_kernel,
                         cudaFuncAttributeMaxDynamicSharedMemorySize, GEMM_SMEM);

    prep_kernel<<<N_E + M_ROWS, 256>>>(w, z);

    dim3 grid(N_E / BN, M_ROWS / BM);      // (64, 64)
    mma_gemm_kernel<<<grid, 256, GEMM_SMEM>>>(out);

    softmax_kernel<<<M_ROWS, 256>>>(out, w);

    finalize_kernel<<<1, 1024>>>(out);
}

// round 14
// speedup vs baseline: 1.0168x; 1.0168x over previous
#include <cuda_runtime.h>
#include <cuda_bf16.h>
#include <math.h>
#include <stdint.h>

// Problem constants
#define M_ROWS 8192      // B*H*W
#define N_E    8192
#define E_DIM  512

// Output layout (flattened tuple, fp32)
#define OFF_PROB ((size_t)3)
#define OFF_D    (OFF_PROB + (size_t)M_ROWS * N_E)
#define OFF_ZQ   (OFF_D    + (size_t)M_ROWS * N_E)
#define OFF_PERP (OFF_ZQ   + (size_t)M_ROWS * E_DIM)
#define OFF_MINE (OFF_PERP + 1)      // divisible by 4 -> float4 stores legal
#define OFF_IDX  (OFF_MINE + (size_t)M_ROWS * N_E)

// ---------------------------------------------------------------------------
// Device scratch (no dynamic allocation allowed)
// ---------------------------------------------------------------------------
static __device__ float g_cbnorm[N_E];
static __device__ float g_winv[N_E];       // 1/||w_row|| : z_q = w*winv
static __device__ float g_znorm[M_ROWS];
static __device__ int   g_counts[N_E];
static __device__ float g_cos[M_ROWS];
// bf16 hi/lo splits for tensor-core GEMM
static __device__ __align__(16) __nv_bfloat16 g_zhi[(size_t)M_ROWS * E_DIM];
static __device__ __align__(16) __nv_bfloat16 g_zlo[(size_t)M_ROWS * E_DIM];
static __device__ __align__(16) __nv_bfloat16 g_bhi[(size_t)N_E   * E_DIM];
static __device__ __align__(16) __nv_bfloat16 g_blo[(size_t)N_E   * E_DIM];

// ---------------------------------------------------------------------------
// PTX helpers (base ISA only: mma.sync / ldmatrix / cp.async)
// ---------------------------------------------------------------------------
__device__ __forceinline__ uint32_t smem_u32(const void* p) {
    uint32_t a;
    asm("{ .reg .u64 t; cvta.to.shared.u64 t, %1; cvt.u32.u64 %0, t; }"
        : "=r"(a) : "l"(p));
    return a;
}
__device__ __forceinline__ void cp16(uint32_t saddr, const void* g) {
    asm volatile("cp.async.cg.shared.global [%0], [%1], 16;"
                 :: "r"(saddr), "l"(g) : "memory");
}
__device__ __forceinline__ void ldsm4(uint32_t* r, uint32_t addr) {
    asm volatile("ldmatrix.sync.aligned.m8n8.x4.shared.b16 {%0,%1,%2,%3}, [%4];"
                 : "=r"(r[0]), "=r"(r[1]), "=r"(r[2]), "=r"(r[3]) : "r"(addr));
}
__device__ __forceinline__ void mma_bf16(float* c, const uint32_t* a, const uint32_t* b) {
    asm volatile(
        "mma.sync.aligned.m16n8k16.row.col.f32.bf16.bf16.f32 "
        "{%0,%1,%2,%3}, {%4,%5,%6,%7}, {%8,%9}, {%0,%1,%2,%3};"
        : "+f"(c[0]), "+f"(c[1]), "+f"(c[2]), "+f"(c[3])
        : "r"(a[0]), "r"(a[1]), "r"(a[2]), "r"(a[3]), "r"(b[0]), "r"(b[1]));
}

// ---------------------------------------------------------------------------
// Fused prep: blocks [0, N_E) normalize codebook rows (bf16 splits + norms);
// blocks [N_E, N_E+M) split z rows.
// ---------------------------------------------------------------------------
__global__ __launch_bounds__(256) void prep_kernel(const float* __restrict__ w,
                                                   const float* __restrict__ z) {
    int b = blockIdx.x;
    int t = threadIdx.x;
    __shared__ float sm[256];

    if (b < N_E) {
        int r = b;
        const float* row = w + (size_t)r * E_DIM;
        float v0 = row[t];
        float v1 = row[t + 256];

        sm[t] = v0 * v0 + v1 * v1;
        __syncthreads();
        #pragma unroll
        for (int s = 128; s > 0; s >>= 1) {
            if (t < s) sm[t] += sm[t + s];
            __syncthreads();
        }
        float norm = sqrtf(sm[0]);
        __syncthreads();

        float c0 = v0 / norm;
        float c1 = v1 / norm;
        size_t base = (size_t)r * E_DIM;

        __nv_bfloat16 h0 = __float2bfloat16(c0);
        __nv_bfloat16 h1 = __float2bfloat16(c1);
        g_bhi[base + t]       = h0;
        g_bhi[base + t + 256] = h1;
        g_blo[base + t]       = __float2bfloat16(c0 - __bfloat162float(h0));
        g_blo[base + t + 256] = __float2bfloat16(c1 - __bfloat162float(h1));

        sm[t] = c0 * c0 + c1 * c1;
        __syncthreads();
        #pragma unroll
        for (int s = 128; s > 0; s >>= 1) {
            if (t < s) sm[t] += sm[t + s];
            __syncthreads();
        }
        if (t == 0) {
            g_cbnorm[r] = sqrtf(sm[0]);
            g_winv[r]   = 1.0f / norm;
        }
    } else {
        int r = b - N_E;
        const float* row = z + (size_t)r * E_DIM;
        float v0 = row[t];
        float v1 = row[t + 256];

        size_t base = (size_t)r * E_DIM;
        __nv_bfloat16 h0 = __float2bfloat16(v0);
        __nv_bfloat16 h1 = __float2bfloat16(v1);
        g_zhi[base + t]       = h0;
        g_zhi[base + t + 256] = h1;
        g_zlo[base + t]       = __float2bfloat16(v0 - __bfloat162float(h0));
        g_zlo[base + t + 256] = __float2bfloat16(v1 - __bfloat162float(h1));

        if (r < N_E / 256) g_counts[r * 256 + t] = 0;

        sm[t] = v0 * v0 + v1 * v1;
        __syncthreads();
        #pragma unroll
        for (int s = 128; s > 0; s >>= 1) {
            if (t < s) sm[t] += sm[t + s];
            __syncthreads();
        }
        if (t == 0) g_znorm[r] = sqrtf(sm[0]);
    }
}

// ---------------------------------------------------------------------------
// mma.sync GEMM (3-term bf16 split): tile 128x128, K chunks of 32,
// 3-stage cp.async pipeline, loads issued 2 chunks ahead.
// XOR swizzle on 64B rows. 96KB smem/CTA -> 2 CTAs/SM.
// min_encodings zeroing interleaved into mainloop.
// ---------------------------------------------------------------------------
#define BM 128
#define BN 128
#define KC 32
#define NCHUNK (E_DIM / KC)        // 16
#define ROWB 64
#define ARR_SZ (128 * ROWB)        // 8192
#define STAGE_SZ (4 * ARR_SZ)      // 32768
#define NSTAGE 3
#define GEMM_SMEM (NSTAGE * STAGE_SZ)  // 98304

__device__ __forceinline__ uint32_t swz(uint32_t row, uint32_t c16) {
    return row * ROWB + (((c16 ^ (row >> 1)) & 3u) << 4);
}

__global__ __launch_bounds__(256, 2) void mma_gemm_kernel(float* __restrict__ out) {
    extern __shared__ char smem[];
    const uint32_t sbase = smem_u32(smem);
    const int tid = threadIdx.x;
    const int lane = tid & 31;
    const int wid = tid >> 5;
    const int wm = wid & 3;
    const int wn = wid >> 2;
    const int r0 = blockIdx.y * BM;
    const int c0 = blockIdx.x * BN;

    float acc[2][8][4];
    #pragma unroll
    for (int a = 0; a < 2; a++)
        #pragma unroll
        for (int b = 0; b < 8; b++)
            #pragma unroll
            for (int e = 0; e < 4; e++) acc[a][b][e] = 0.0f;

    auto load_chunk = [&](int c, int stage) {
        uint32_t sb = sbase + (uint32_t)stage * STAGE_SZ;
        #pragma unroll
        for (int i = 0; i < 2; i++) {
            int slot = tid + i * 256;
            uint32_t row = (uint32_t)slot >> 2;
            uint32_t u   = (uint32_t)slot & 3;
            uint32_t so = swz(row, u);
            size_t ga = (size_t)(r0 + row) * E_DIM + c * KC + u * 8;
            size_t gb = (size_t)(c0 + row) * E_DIM + c * KC + u * 8;
            cp16(sb + so,              g_zhi + ga);
            cp16(sb + ARR_SZ + so,     g_zlo + ga);
            cp16(sb + 2 * ARR_SZ + so, g_bhi + gb);
            cp16(sb + 3 * ARR_SZ + so, g_blo + gb);
        }
        asm volatile("cp.async.commit_group;" ::: "memory");
    };

    const uint32_t rowA = (uint32_t)(wm * 32 + (lane & 15));
    const uint32_t rowB = (uint32_t)(wn * 64 + (lane & 7) + ((lane >> 4) << 3));
    const uint32_t xA = (rowA >> 1) & 3u;
    const uint32_t xB = (rowB >> 1) & 3u;
    const uint32_t cA0 = (uint32_t)(lane >> 4);
    const uint32_t cB0 = (uint32_t)((lane >> 3) & 1);
    const uint32_t aBase = rowA * ROWB;
    const uint32_t bBase = rowB * ROWB;

    auto compute = [&](int stage) {
        uint32_t sb = sbase + (uint32_t)stage * STAGE_SZ;
        uint32_t Ahi = sb;
        uint32_t Alo = sb + ARR_SZ;
        uint32_t Bhi = sb + 2 * ARR_SZ;
        uint32_t Blo = sb + 3 * ARR_SZ;
        #pragma unroll
        for (int ks = 0; ks < 2; ks++) {
            uint32_t aOff = aBase + (((cA0 + 2 * ks) ^ xA) & 3u) * 16;
            uint32_t bOff = bBase + (((cB0 + 2 * ks) ^ xB) & 3u) * 16;

            uint32_t ah[2][4], al[2][4];
            ldsm4(ah[0], Ahi + aOff);
            ldsm4(ah[1], Ahi + aOff + 16 * ROWB);
            ldsm4(al[0], Alo + aOff);
            ldsm4(al[1], Alo + aOff + 16 * ROWB);

            uint32_t bh[2][4], bl[2][4];
            ldsm4(bh[0], Bhi + bOff);
            ldsm4(bl[0], Blo + bOff);

            #pragma unroll
            for (int np = 0; np < 4; np++) {
                const int cur = np & 1;
                const int nxt = cur ^ 1;
                if (np < 3) {
                    ldsm4(bh[nxt], Bhi + bOff + (np + 1) * 16 * ROWB);
                    ldsm4(bl[nxt], Blo + bOff + (np + 1) * 16 * ROWB);
                }
                #pragma unroll
                for (int mt = 0; mt < 2; mt++)
                    #pragma unroll
                    for (int s = 0; s < 2; s++)
                        mma_bf16(acc[mt][np * 2 + s], ah[mt], bh[cur] + 2 * s);  // hi*hi
                #pragma unroll
                for (int mt = 0; mt < 2; mt++)
                    #pragma unroll
                    for (int s = 0; s < 2; s++)
                        mma_bf16(acc[mt][np * 2 + s], al[mt], bh[cur] + 2 * s);  // lo*hi
                #pragma unroll
                for (int mt = 0; mt < 2; mt++)
                    #pragma unroll
                    for (int s = 0; s < 2; s++)
                        mma_bf16(acc[mt][np * 2 + s], ah[mt], bl[cur] + 2 * s);  // hi*lo
            }
        }
    };

    float* MINE = out + OFF_MINE;
    const int zrow = wid;
    const int zcol = lane * 4;

    load_chunk(0, 0);
    load_chunk(1, 1);
    #pragma unroll 1
    for (int c = 0; c < NCHUNK; c++) {
        if (c + 1 < NCHUNK) {
            asm volatile("cp.async.wait_group 1;" ::: "memory");
        } else {
            asm volatile("cp.async.wait_group 0;" ::: "memory");
        }
        __syncthreads();
        if (c + 2 < NCHUNK) load_chunk(c + 2, (c + 2) % NSTAGE);
        {
            float4 z4 = make_float4(0.f, 0.f, 0.f, 0.f);
            *reinterpret_cast<float4*>(
                MINE + (size_t)(r0 + c * 8 + zrow) * N_E + c0 + zcol) = z4;
        }
        compute(c % NSTAGE);
    }

    float* D = out + OFF_D;
    const int gr = lane >> 2;
    const int gc = (lane & 3) * 2;
    #pragma unroll
    for (int mt = 0; mt < 2; mt++) {
        int rA = r0 + wm * 32 + mt * 16 + gr;
        int rB = rA + 8;
        float znA = g_znorm[rA];
        float znB = g_znorm[rB];
        #pragma unroll
        for (int n8 = 0; n8 < 8; n8++) {
            int cc = c0 + wn * 64 + n8 * 8 + gc;
            float cn0 = g_cbnorm[cc];
            float cn1 = g_cbnorm[cc + 1];
            float* a4 = acc[mt][n8];
            D[(size_t)rA * N_E + cc]     = a4[0] / (znA * cn0 + 1e-6f);
            D[(size_t)rA * N_E + cc + 1] = a4[1] / (znA * cn1 + 1e-6f);
            D[(size_t)rB * N_E + cc]     = a4[2] / (znB * cn0 + 1e-6f);
            D[(size_t)rB * N_E + cc + 1] = a4[3] / (znB * cn1 + 1e-6f);
        }
    }
}

// ---------------------------------------------------------------------------
// Polynomial exp on [-1,1] (degree-10 Taylor, FMA pipe; avoids MUFU wall)
// ---------------------------------------------------------------------------
__device__ __forceinline__ float exp_poly(float x) {
    const float c10 = 2.7557319e-7f, c9 = 2.7557319e-6f, c8 = 2.4801587e-5f;
    const float c7 = 1.9841270e-4f,  c6 = 1.3888889e-3f, c5 = 8.3333333e-3f;
    const float c4 = 4.1666668e-2f,  c3 = 1.6666667e-1f, c2 = 0.5f;
    float p = c10;
    p = fmaf(p, x, c9);
    p = fmaf(p, x, c8);
    p = fmaf(p, x, c7);
    p = fmaf(p, x, c6);
    p = fmaf(p, x, c5);
    p = fmaf(p, x, c4);
    p = fmaf(p, x, c3);
    p = fmaf(p, x, c2);
    p = fmaf(p, x, 1.0f);
    p = fmaf(p, x, 1.0f);
    return p;
}

// ---------------------------------------------------------------------------
// Fused per-row (256 threads): single DRAM read of d; exp values cached in
// SHARED memory (32KB) instead of registers -> regs ~30, more resident CTAs,
// better latency hiding. argmax (first-index tie-break), histogram, idx,
// one-hot 1.0, z_q = w[idx]*winv[idx], cosine via rescale identity, softmax.
// ---------------------------------------------------------------------------
__global__ __launch_bounds__(256) void softmax_kernel(float* __restrict__ out,
                                                      const float* __restrict__ w) {
    __shared__ float srow[N_E];        // exp cache (32 KB)
    __shared__ float sred[256];
    __shared__ int   sidx[256];

    int r = blockIdx.x;
    int t = threadIdx.x;
    const float* drow = out + OFF_D + (size_t)r * N_E;

    // single pass over d: max/argmax + exp into smem + sum
    float best = -2.0f;
    int bi = 0;
    float sum = 0.0f;
    #pragma unroll 4
    for (int j = 0; j < 32; j++) {
        int i = t + j * 256;
        float v = drow[i];
        if (v > best) { best = v; bi = i; }   // j ascending => first index kept
        float ev = exp_poly(v);
        srow[i] = ev;
        sum += ev;
    }
    sred[t] = best; sidx[t] = bi;
    __syncthreads();
    for (int s = 128; s > 0; s >>= 1) {
        if (t < s) {
            float v = sred[t + s]; int ii = sidx[t + s];
            if (v > sred[t] || (v == sred[t] && ii < sidx[t])) {
                sred[t] = v; sidx[t] = ii;
            }
        }
        __syncthreads();
    }
    int idx = sidx[0];
    if (t == 0) {
        atomicAdd(&g_counts[idx], 1);
        out[OFF_IDX + r] = (float)idx;
        out[OFF_MINE + (size_t)r * N_E + idx] = 1.0f;
        float zn  = g_znorm[r];
        float cbn = g_cbnorm[idx];
        float p   = zn * cbn;
        g_cos[r] = sred[0] * (p + 1e-6f) / p;
    }

    // z_q_st row = w[idx] * (1/||w[idx]||)  (identical arithmetic to cb[idx])
    {
        float winv = g_winv[idx];
        const float* wrow = w + (size_t)idx * E_DIM;
        float* o = out + OFF_ZQ + (size_t)r * E_DIM;
        o[t]       = wrow[t] * winv;
        o[t + 256] = wrow[t + 256] * winv;
    }

    __syncthreads();
    sred[t] = sum;
    __syncthreads();
    for (int s = 128; s > 0; s >>= 1) {
        if (t < s) sred[t] += sred[t + s];
        __syncthreads();
    }
    float inv = 1.0f / sred[0];

    float* prow = out + OFF_PROB + (size_t)r * N_E;
    #pragma unroll 4
    for (int j = 0; j < 32; j++) {
        int i = t + j * 256;
        prow[i] = srow[i] * inv;
    }
}

// ---------------------------------------------------------------------------
// Scalars — 1024 threads so the logf chains parallelize.
// ---------------------------------------------------------------------------
__global__ __launch_bounds__(1024) void finalize_kernel(float* __restrict__ out) {
    int t = threadIdx.x;
    __shared__ float s1[1024], s2[1024], s3[1024];

    float kl = 0.0f, ent = 0.0f, cs = 0.0f;
    const float invM  = 1.0f / (float)M_ROWS;
    const float invNE = 1.0f / (float)N_E;
    #pragma unroll
    for (int j = t; j < N_E; j += 1024) {
        float em = (float)g_counts[j] * invM;
        kl  += em * logf(invNE / (em + 1e-6f));
        ent += em * logf(em + 1e-6f);
    }
    #pragma unroll
    for (int j = t; j < M_ROWS; j += 1024) cs += g_cos[j];

    s1[t] = kl; s2[t] = ent; s3[t] = cs;
    __syncthreads();
    for (int s = 512; s > 0; s >>= 1) {
        if (t < s) { s1[t] += s1[t + s]; s2[t] += s2[t + s]; s3[t] += s3[t + s]; }
        __syncthreads();
    }
    if (t == 0) {
        float mc = s3[0] * invM;
        out[0] = (1.0f - mc) + 0.25f * (1.0f - mc);
        out[1] = 0.0f;
        out[2] = -s1[0];
        out[OFF_PERP] = expf(-s2[0]);
    }
}

// ---------------------------------------------------------------------------
extern "C" void kernel_launch(void* const* d_in, const int* in_sizes, int n_in,
                              void* d_out, int out_size) {
    const float* z = (const float*)d_in[0];
    const float* w = (const float*)d_in[1];
    float* out = (float*)d_out;

    cudaFuncSetAttribute(mma_gemm_kernel,
                         cudaFuncAttributeMaxDynamicSharedMemorySize, GEMM_SMEM);

    prep_kernel<<<N_E + M_ROWS, 256>>>(w, z);

    dim3 grid(N_E / BN, M_ROWS / BM);      // (64, 64)
    mma_gemm_kernel<<<grid, 256, GEMM_SMEM>>>(out);

    softmax_kernel<<<M_ROWS, 256>>>(out, w);

    finalize_kernel<<<1, 1024>>>(out);
}

// round 15
// speedup vs baseline: 1.0511x; 1.0338x over previous
#include <cuda_runtime.h>
#include <cuda_bf16.h>
#include <math.h>
#include <stdint.h>

// Problem constants
#define M_ROWS 8192      // B*H*W
#define N_E    8192
#define E_DIM  512

// Output layout (flattened tuple, fp32)
#define OFF_PROB ((size_t)3)
#define OFF_D    (OFF_PROB + (size_t)M_ROWS * N_E)
#define OFF_ZQ   (OFF_D    + (size_t)M_ROWS * N_E)
#define OFF_PERP (OFF_ZQ   + (size_t)M_ROWS * E_DIM)
#define OFF_MINE (OFF_PERP + 1)      // divisible by 4 -> float4 stores legal
#define OFF_IDX  (OFF_MINE + (size_t)M_ROWS * N_E)

// ---------------------------------------------------------------------------
// Device scratch (no dynamic allocation allowed)
// ---------------------------------------------------------------------------
static __device__ float g_cbnorm[N_E];
static __device__ float g_winv[N_E];       // 1/||w_row|| : z_q = w*winv
static __device__ float g_znorm[M_ROWS];
static __device__ int   g_counts[N_E];
static __device__ float g_cos[M_ROWS];
// bf16 hi/lo splits for tensor-core GEMM
static __device__ __align__(16) __nv_bfloat16 g_zhi[(size_t)M_ROWS * E_DIM];
static __device__ __align__(16) __nv_bfloat16 g_zlo[(size_t)M_ROWS * E_DIM];
static __device__ __align__(16) __nv_bfloat16 g_bhi[(size_t)N_E   * E_DIM];
static __device__ __align__(16) __nv_bfloat16 g_blo[(size_t)N_E   * E_DIM];

// ---------------------------------------------------------------------------
// PTX helpers (base ISA only: mma.sync / ldmatrix / cp.async)
// ---------------------------------------------------------------------------
__device__ __forceinline__ uint32_t smem_u32(const void* p) {
    uint32_t a;
    asm("{ .reg .u64 t; cvta.to.shared.u64 t, %1; cvt.u32.u64 %0, t; }"
        : "=r"(a) : "l"(p));
    return a;
}
__device__ __forceinline__ void cp16(uint32_t saddr, const void* g) {
    asm volatile("cp.async.cg.shared.global [%0], [%1], 16;"
                 :: "r"(saddr), "l"(g) : "memory");
}
__device__ __forceinline__ void ldsm4(uint32_t* r, uint32_t addr) {
    asm volatile("ldmatrix.sync.aligned.m8n8.x4.shared.b16 {%0,%1,%2,%3}, [%4];"
                 : "=r"(r[0]), "=r"(r[1]), "=r"(r[2]), "=r"(r[3]) : "r"(addr));
}
__device__ __forceinline__ void mma_bf16(float* c, const uint32_t* a, const uint32_t* b) {
    asm volatile(
        "mma.sync.aligned.m16n8k16.row.col.f32.bf16.bf16.f32 "
        "{%0,%1,%2,%3}, {%4,%5,%6,%7}, {%8,%9}, {%0,%1,%2,%3};"
        : "+f"(c[0]), "+f"(c[1]), "+f"(c[2]), "+f"(c[3])
        : "r"(a[0]), "r"(a[1]), "r"(a[2]), "r"(a[3]), "r"(b[0]), "r"(b[1]));
}

// ---------------------------------------------------------------------------
// Fused prep: blocks [0, N_E) normalize codebook rows (bf16 splits + norms,
// no fp32 cb array); blocks [N_E, N_E+M) split z rows.
// ---------------------------------------------------------------------------
__global__ __launch_bounds__(256) void prep_kernel(const float* __restrict__ w,
                                                   const float* __restrict__ z) {
    int b = blockIdx.x;
    int t = threadIdx.x;
    __shared__ float sm[256];

    if (b < N_E) {
        int r = b;
        const float* row = w + (size_t)r * E_DIM;
        float v0 = row[t];
        float v1 = row[t + 256];

        sm[t] = v0 * v0 + v1 * v1;
        __syncthreads();
        #pragma unroll
        for (int s = 128; s > 0; s >>= 1) {
            if (t < s) sm[t] += sm[t + s];
            __syncthreads();
        }
        float norm = sqrtf(sm[0]);
        __syncthreads();

        float c0 = v0 / norm;
        float c1 = v1 / norm;
        size_t base = (size_t)r * E_DIM;

        __nv_bfloat16 h0 = __float2bfloat16(c0);
        __nv_bfloat16 h1 = __float2bfloat16(c1);
        g_bhi[base + t]       = h0;
        g_bhi[base + t + 256] = h1;
        g_blo[base + t]       = __float2bfloat16(c0 - __bfloat162float(h0));
        g_blo[base + t + 256] = __float2bfloat16(c1 - __bfloat162float(h1));

        sm[t] = c0 * c0 + c1 * c1;
        __syncthreads();
        #pragma unroll
        for (int s = 128; s > 0; s >>= 1) {
            if (t < s) sm[t] += sm[t + s];
            __syncthreads();
        }
        if (t == 0) {
            g_cbnorm[r] = sqrtf(sm[0]);
            g_winv[r]   = 1.0f / norm;
        }
    } else {
        int r = b - N_E;
        const float* row = z + (size_t)r * E_DIM;
        float v0 = row[t];
        float v1 = row[t + 256];

        size_t base = (size_t)r * E_DIM;
        __nv_bfloat16 h0 = __float2bfloat16(v0);
        __nv_bfloat16 h1 = __float2bfloat16(v1);
        g_zhi[base + t]       = h0;
        g_zhi[base + t + 256] = h1;
        g_zlo[base + t]       = __float2bfloat16(v0 - __bfloat162float(h0));
        g_zlo[base + t + 256] = __float2bfloat16(v1 - __bfloat162float(h1));

        if (r < N_E / 256) g_counts[r * 256 + t] = 0;

        sm[t] = v0 * v0 + v1 * v1;
        __syncthreads();
        #pragma unroll
        for (int s = 128; s > 0; s >>= 1) {
            if (t < s) sm[t] += sm[t + s];
            __syncthreads();
        }
        if (t == 0) g_znorm[r] = sqrtf(sm[0]);
    }
}

// ---------------------------------------------------------------------------
// mma.sync GEMM (3-term bf16 split): tile 128x128, K chunks of 32,
// 3-stage cp.async pipeline, loads issued 2 chunks ahead.
// XOR swizzle on 64B rows. 96KB smem/CTA -> 2 CTAs/SM.
// min_encodings zeroing interleaved into mainloop.
// ---------------------------------------------------------------------------
#define BM 128
#define BN 128
#define KC 32
#define NCHUNK (E_DIM / KC)        // 16
#define ROWB 64
#define ARR_SZ (128 * ROWB)        // 8192
#define STAGE_SZ (4 * ARR_SZ)      // 32768
#define NSTAGE 3
#define GEMM_SMEM (NSTAGE * STAGE_SZ)  // 98304

__device__ __forceinline__ uint32_t swz(uint32_t row, uint32_t c16) {
    return row * ROWB + (((c16 ^ (row >> 1)) & 3u) << 4);
}

__global__ __launch_bounds__(256, 2) void mma_gemm_kernel(float* __restrict__ out) {
    extern __shared__ char smem[];
    const uint32_t sbase = smem_u32(smem);
    const int tid = threadIdx.x;
    const int lane = tid & 31;
    const int wid = tid >> 5;
    const int wm = wid & 3;
    const int wn = wid >> 2;
    const int r0 = blockIdx.y * BM;
    const int c0 = blockIdx.x * BN;

    float acc[2][8][4];
    #pragma unroll
    for (int a = 0; a < 2; a++)
        #pragma unroll
        for (int b = 0; b < 8; b++)
            #pragma unroll
            for (int e = 0; e < 4; e++) acc[a][b][e] = 0.0f;

    auto load_chunk = [&](int c, int stage) {
        uint32_t sb = sbase + (uint32_t)stage * STAGE_SZ;
        #pragma unroll
        for (int i = 0; i < 2; i++) {
            int slot = tid + i * 256;
            uint32_t row = (uint32_t)slot >> 2;
            uint32_t u   = (uint32_t)slot & 3;
            uint32_t so = swz(row, u);
            size_t ga = (size_t)(r0 + row) * E_DIM + c * KC + u * 8;
            size_t gb = (size_t)(c0 + row) * E_DIM + c * KC + u * 8;
            cp16(sb + so,              g_zhi + ga);
            cp16(sb + ARR_SZ + so,     g_zlo + ga);
            cp16(sb + 2 * ARR_SZ + so, g_bhi + gb);
            cp16(sb + 3 * ARR_SZ + so, g_blo + gb);
        }
        asm volatile("cp.async.commit_group;" ::: "memory");
    };

    const uint32_t rowA = (uint32_t)(wm * 32 + (lane & 15));
    const uint32_t rowB = (uint32_t)(wn * 64 + (lane & 7) + ((lane >> 4) << 3));
    const uint32_t xA = (rowA >> 1) & 3u;
    const uint32_t xB = (rowB >> 1) & 3u;
    const uint32_t cA0 = (uint32_t)(lane >> 4);
    const uint32_t cB0 = (uint32_t)((lane >> 3) & 1);
    const uint32_t aBase = rowA * ROWB;
    const uint32_t bBase = rowB * ROWB;

    auto compute = [&](int stage) {
        uint32_t sb = sbase + (uint32_t)stage * STAGE_SZ;
        uint32_t Ahi = sb;
        uint32_t Alo = sb + ARR_SZ;
        uint32_t Bhi = sb + 2 * ARR_SZ;
        uint32_t Blo = sb + 3 * ARR_SZ;
        #pragma unroll
        for (int ks = 0; ks < 2; ks++) {
            uint32_t aOff = aBase + (((cA0 + 2 * ks) ^ xA) & 3u) * 16;
            uint32_t bOff = bBase + (((cB0 + 2 * ks) ^ xB) & 3u) * 16;

            uint32_t ah[2][4], al[2][4];
            ldsm4(ah[0], Ahi + aOff);
            ldsm4(ah[1], Ahi + aOff + 16 * ROWB);
            ldsm4(al[0], Alo + aOff);
            ldsm4(al[1], Alo + aOff + 16 * ROWB);

            uint32_t bh[2][4], bl[2][4];
            ldsm4(bh[0], Bhi + bOff);
            ldsm4(bl[0], Blo + bOff);

            #pragma unroll
            for (int np = 0; np < 4; np++) {
                const int cur = np & 1;
                const int nxt = cur ^ 1;
                if (np < 3) {
                    ldsm4(bh[nxt], Bhi + bOff + (np + 1) * 16 * ROWB);
                    ldsm4(bl[nxt], Blo + bOff + (np + 1) * 16 * ROWB);
                }
                #pragma unroll
                for (int mt = 0; mt < 2; mt++)
                    #pragma unroll
                    for (int s = 0; s < 2; s++)
                        mma_bf16(acc[mt][np * 2 + s], ah[mt], bh[cur] + 2 * s);  // hi*hi
                #pragma unroll
                for (int mt = 0; mt < 2; mt++)
                    #pragma unroll
                    for (int s = 0; s < 2; s++)
                        mma_bf16(acc[mt][np * 2 + s], al[mt], bh[cur] + 2 * s);  // lo*hi
                #pragma unroll
                for (int mt = 0; mt < 2; mt++)
                    #pragma unroll
                    for (int s = 0; s < 2; s++)
                        mma_bf16(acc[mt][np * 2 + s], ah[mt], bl[cur] + 2 * s);  // hi*lo
            }
        }
    };

    float* MINE = out + OFF_MINE;
    const int zrow = wid;
    const int zcol = lane * 4;

    load_chunk(0, 0);
    load_chunk(1, 1);
    #pragma unroll 1
    for (int c = 0; c < NCHUNK; c++) {
        if (c + 1 < NCHUNK) {
            asm volatile("cp.async.wait_group 1;" ::: "memory");
        } else {
            asm volatile("cp.async.wait_group 0;" ::: "memory");
        }
        __syncthreads();
        if (c + 2 < NCHUNK) load_chunk(c + 2, (c + 2) % NSTAGE);
        {
            float4 z4 = make_float4(0.f, 0.f, 0.f, 0.f);
            *reinterpret_cast<float4*>(
                MINE + (size_t)(r0 + c * 8 + zrow) * N_E + c0 + zcol) = z4;
        }
        compute(c % NSTAGE);
    }

    float* D = out + OFF_D;
    const int gr = lane >> 2;
    const int gc = (lane & 3) * 2;
    #pragma unroll
    for (int mt = 0; mt < 2; mt++) {
        int rA = r0 + wm * 32 + mt * 16 + gr;
        int rB = rA + 8;
        float znA = g_znorm[rA];
        float znB = g_znorm[rB];
        #pragma unroll
        for (int n8 = 0; n8 < 8; n8++) {
            int cc = c0 + wn * 64 + n8 * 8 + gc;
            float cn0 = g_cbnorm[cc];
            float cn1 = g_cbnorm[cc + 1];
            float* a4 = acc[mt][n8];
            D[(size_t)rA * N_E + cc]     = a4[0] / (znA * cn0 + 1e-6f);
            D[(size_t)rA * N_E + cc + 1] = a4[1] / (znA * cn1 + 1e-6f);
            D[(size_t)rB * N_E + cc]     = a4[2] / (znB * cn0 + 1e-6f);
            D[(size_t)rB * N_E + cc + 1] = a4[3] / (znB * cn1 + 1e-6f);
        }
    }
}

// ---------------------------------------------------------------------------
// Polynomial exp on [-1,1] (degree-10 Taylor, FMA pipe; avoids MUFU wall)
// ---------------------------------------------------------------------------
__device__ __forceinline__ float exp_poly(float x) {
    const float c10 = 2.7557319e-7f, c9 = 2.7557319e-6f, c8 = 2.4801587e-5f;
    const float c7 = 1.9841270e-4f,  c6 = 1.3888889e-3f, c5 = 8.3333333e-3f;
    const float c4 = 4.1666668e-2f,  c3 = 1.6666667e-1f, c2 = 0.5f;
    float p = c10;
    p = fmaf(p, x, c9);
    p = fmaf(p, x, c8);
    p = fmaf(p, x, c7);
    p = fmaf(p, x, c6);
    p = fmaf(p, x, c5);
    p = fmaf(p, x, c4);
    p = fmaf(p, x, c3);
    p = fmaf(p, x, c2);
    p = fmaf(p, x, 1.0f);
    p = fmaf(p, x, 1.0f);
    return p;
}

// ---------------------------------------------------------------------------
// Fused per-row (256 threads — ROUND-12 PROVEN SHAPE: single DRAM read of d,
// e[32] register cache): argmax (first-index tie-break), histogram, idx,
// one-hot 1.0, z_q = w[idx]*winv[idx], cosine via rescale identity, softmax.
// ---------------------------------------------------------------------------
__global__ __launch_bounds__(256) void softmax_kernel(float* __restrict__ out,
                                                      const float* __restrict__ w) {
    __shared__ float sred[256];
    __shared__ int   sidx[256];

    int r = blockIdx.x;
    int t = threadIdx.x;
    const float* drow = out + OFF_D + (size_t)r * N_E;

    float e[32];
    float best = -2.0f;
    int bi = 0;
    float sum = 0.0f;
    #pragma unroll
    for (int j = 0; j < 32; j++) {
        int i = t + j * 256;
        float v = drow[i];
        if (v > best) { best = v; bi = i; }   // j ascending => first index kept
        float ev = exp_poly(v);
        e[j] = ev;
        sum += ev;
    }
    sred[t] = best; sidx[t] = bi;
    __syncthreads();
    for (int s = 128; s > 0; s >>= 1) {
        if (t < s) {
            float v = sred[t + s]; int ii = sidx[t + s];
            if (v > sred[t] || (v == sred[t] && ii < sidx[t])) {
                sred[t] = v; sidx[t] = ii;
            }
        }
        __syncthreads();
    }
    int idx = sidx[0];
    if (t == 0) {
        atomicAdd(&g_counts[idx], 1);
        out[OFF_IDX + r] = (float)idx;
        out[OFF_MINE + (size_t)r * N_E + idx] = 1.0f;
        float zn  = g_znorm[r];
        float cbn = g_cbnorm[idx];
        float p   = zn * cbn;
        g_cos[r] = sred[0] * (p + 1e-6f) / p;
    }

    // z_q_st row = w[idx] * (1/||w[idx]||)  (identical arithmetic to cb[idx])
    {
        float winv = g_winv[idx];
        const float* wrow = w + (size_t)idx * E_DIM;
        float* o = out + OFF_ZQ + (size_t)r * E_DIM;
        o[t]       = wrow[t] * winv;
        o[t + 256] = wrow[t + 256] * winv;
    }

    __syncthreads();
    sred[t] = sum;
    __syncthreads();
    for (int s = 128; s > 0; s >>= 1) {
        if (t < s) sred[t] += sred[t + s];
        __syncthreads();
    }
    float inv = 1.0f / sred[0];

    float* prow = out + OFF_PROB + (size_t)r * N_E;
    #pragma unroll
    for (int j = 0; j < 32; j++) prow[t + j * 256] = e[j] * inv;
}

// ---------------------------------------------------------------------------
// Scalars — 1024 threads so the logf chains parallelize.
// ---------------------------------------------------------------------------
__global__ __launch_bounds__(1024) void finalize_kernel(float* __restrict__ out) {
    int t = threadIdx.x;
    __shared__ float s1[1024], s2[1024], s3[1024];

    float kl = 0.0f, ent = 0.0f, cs = 0.0f;
    const float invM  = 1.0f / (float)M_ROWS;
    const float invNE = 1.0f / (float)N_E;
    #pragma unroll
    for (int j = t; j < N_E; j += 1024) {
        float em = (float)g_counts[j] * invM;
        kl  += em * logf(invNE / (em + 1e-6f));
        ent += em * logf(em + 1e-6f);
    }
    #pragma unroll
    for (int j = t; j < M_ROWS; j += 1024) cs += g_cos[j];

    s1[t] = kl; s2[t] = ent; s3[t] = cs;
    __syncthreads();
    for (int s = 512; s > 0; s >>= 1) {
        if (t < s) { s1[t] += s1[t + s]; s2[t] += s2[t + s]; s3[t] += s3[t + s]; }
        __syncthreads();
    }
    if (t == 0) {
        float mc = s3[0] * invM;
        out[0] = (1.0f - mc) + 0.25f * (1.0f - mc);
        out[1] = 0.0f;
        out[2] = -s1[0];
        out[OFF_PERP] = expf(-s2[0]);
    }
}

// ---------------------------------------------------------------------------
extern "C" void kernel_launch(void* const* d_in, const int* in_sizes, int n_in,
                              void* d_out, int out_size) {
    const float* z = (const float*)d_in[0];
    const float* w = (const float*)d_in[1];
    float* out = (float*)d_out;

    cudaFuncSetAttribute(mma_gemm_kernel,
                         cudaFuncAttributeMaxDynamicSharedMemorySize, GEMM_SMEM);

    prep_kernel<<<N_E + M_ROWS, 256>>>(w, z);

    dim3 grid(N_E / BN, M_ROWS / BM);      // (64, 64)
    mma_gemm_kernel<<<grid, 256, GEMM_SMEM>>>(out);

    softmax_kernel<<<M_ROWS, 256>>>(out, w);

    finalize_kernel<<<1, 1024>>>(out);
}